// round 5
// baseline (speedup 1.0000x reference)
#include <cuda_runtime.h>

// max_general_2x2: reference relu chain collapses exactly to a
// 2x2 stride-2 fp32 max-pool:
//   relu(a-b)+relu(b)-relu(-b) = max(a,b); nested -> out = max(a,b,c,d)
//
// Input  x: (32, 64, 112, 112) fp32 (102.8 MB)
// Output  : (32, 64, 56, 56)   fp32 ( 25.7 MB)
// HBM-bound. R4: 19.58us kernel @ DRAM 71.7%. This round: MLP 4->8,
// waves 5.3->2.65, to push DRAM% toward ceiling.

#define NC_PLANES   (32 * 64)      // 2048 planes
#define IN_W        112
#define IN_PLANE    (112 * 112)    // 12544
#define OUT_W       56
#define V8_PER_ROW  (OUT_W / 8)    // 7 chunks of 8 output cols per row
#define TOTAL_V8    (NC_PLANES * OUT_W * V8_PER_ROW)  // 802,816 threads

__global__ __launch_bounds__(256) void maxpool2x2_kernel(
    const float* __restrict__ in, float4* __restrict__ out, int total)
{
    int idx = blockIdx.x * blockDim.x + threadIdx.x;
    if (idx >= total) return;

    // idx -> (plane, oh, j); j indexes an 8-output-col chunk (16 input cols)
    int j     = idx % V8_PER_ROW;           // 0..6
    int t     = idx / V8_PER_ROW;
    int oh    = t % OUT_W;                  // 0..55
    int plane = t / OUT_W;                  // 0..2047

    // Input rows 2*oh, 2*oh+1; cols 16*j .. 16*j+15. 16B aligned.
    const float4* r0 = reinterpret_cast<const float4*>(
        in + (size_t)plane * IN_PLANE + (2 * oh) * IN_W + 16 * j);
    const float4* r1 = reinterpret_cast<const float4*>(
        reinterpret_cast<const float*>(r0) + IN_W);

    // 8 independent LDG.128, front-batched (MLP_p1 = 8)
    float4 a0 = r0[0];
    float4 a1 = r0[1];
    float4 a2 = r0[2];
    float4 a3 = r0[3];
    float4 b0 = r1[0];
    float4 b1 = r1[1];
    float4 b2 = r1[2];
    float4 b3 = r1[3];

    float4 o0, o1;
    o0.x = fmaxf(fmaxf(a0.x, a0.y), fmaxf(b0.x, b0.y));
    o0.y = fmaxf(fmaxf(a0.z, a0.w), fmaxf(b0.z, b0.w));
    o0.z = fmaxf(fmaxf(a1.x, a1.y), fmaxf(b1.x, b1.y));
    o0.w = fmaxf(fmaxf(a1.z, a1.w), fmaxf(b1.z, b1.w));
    o1.x = fmaxf(fmaxf(a2.x, a2.y), fmaxf(b2.x, b2.y));
    o1.y = fmaxf(fmaxf(a2.z, a2.w), fmaxf(b2.z, b2.w));
    o1.z = fmaxf(fmaxf(a3.x, a3.y), fmaxf(b3.x, b3.y));
    o1.w = fmaxf(fmaxf(a3.z, a3.w), fmaxf(b3.z, b3.w));

    // Output: 8 contiguous floats = 2 consecutive float4 (STG.128 x2)
    size_t obase = ((size_t)plane * OUT_W + oh) * (OUT_W / 4) + 2 * j;
    out[obase]     = o0;
    out[obase + 1] = o1;
}

extern "C" void kernel_launch(void* const* d_in, const int* in_sizes, int n_in,
                              void* d_out, int out_size)
{
    const float* x = (const float*)d_in[0];
    float4* out = (float4*)d_out;

    const int total = TOTAL_V8;             // 802,816 threads
    const int threads = 256;
    const int blocks = (total + threads - 1) / threads;  // 3136
    maxpool2x2_kernel<<<blocks, threads>>>(x, out, total);
}

// round 6
// speedup vs baseline: 1.0825x; 1.0825x over previous
#include <cuda_runtime.h>

// max_general_2x2: reference relu chain collapses exactly to a
// 2x2 stride-2 fp32 max-pool: out = max(a,b,c,d).
//
// Input  x: (32, 64, 112, 112) fp32 (102.8 MB)
// Output  : (32, 64, 56, 56)   fp32 ( 25.7 MB)
//
// R4 (this mapping, no hints): 19.58us kernel, DRAM 71.7%, L1 41.3%.
// R5 (8 LDG/thread) REGRESSED: warp footprint fragmentation -> L1 69.8%.
// R6 = R4 + streaming cache hints (__ldcs/__stcs): zero-reuse stream,
// evict-first in L2 to cut read/write thrash.

#define NC_PLANES   (32 * 64)      // 2048 planes
#define IN_W        112
#define IN_PLANE    (112 * 112)    // 12544
#define OUT_W       56
#define V4_PER_ROW  (OUT_W / 4)    // 14 float4 per output row
#define TOTAL_V4    (NC_PLANES * OUT_W * V4_PER_ROW)  // 1,605,632

__global__ __launch_bounds__(256) void maxpool2x2_kernel(
    const float* __restrict__ in, float4* __restrict__ out, int total)
{
    int idx = blockIdx.x * blockDim.x + threadIdx.x;
    if (idx >= total) return;

    // idx -> (plane, oh, j) where j indexes a float4 (4 output cols)
    int j     = idx % V4_PER_ROW;           // 0..13
    int t     = idx / V4_PER_ROW;
    int oh    = t % OUT_W;                  // 0..55
    int plane = t / OUT_W;                  // 0..2047

    // Input rows 2*oh, 2*oh+1; cols 8*j .. 8*j+7. All 16B aligned.
    const float4* ip0 = reinterpret_cast<const float4*>(
        in + (size_t)plane * IN_PLANE + (2 * oh) * IN_W + 8 * j);
    const float4* ip1 = reinterpret_cast<const float4*>(
        reinterpret_cast<const float*>(ip0) + IN_W);

    // 4 independent LDG.128.CS, front-batched (MLP=4), evict-first
    float4 a0 = __ldcs(ip0);
    float4 a1 = __ldcs(ip0 + 1);
    float4 b0 = __ldcs(ip1);
    float4 b1 = __ldcs(ip1 + 1);

    float4 o;
    o.x = fmaxf(fmaxf(a0.x, a0.y), fmaxf(b0.x, b0.y));
    o.y = fmaxf(fmaxf(a0.z, a0.w), fmaxf(b0.z, b0.w));
    o.z = fmaxf(fmaxf(a1.x, a1.y), fmaxf(b1.x, b1.y));
    o.w = fmaxf(fmaxf(a1.z, a1.w), fmaxf(b1.z, b1.w));

    __stcs(out + idx, o);
}

extern "C" void kernel_launch(void* const* d_in, const int* in_sizes, int n_in,
                              void* d_out, int out_size)
{
    const float* x = (const float*)d_in[0];
    float4* out = (float4*)d_out;

    const int total = TOTAL_V4;             // 1,605,632 float4 outputs
    const int threads = 256;
    const int blocks = (total + threads - 1) / threads;  // 6272
    maxpool2x2_kernel<<<blocks, threads>>>(x, out, total);
}

// round 12
// speedup vs baseline: 1.0946x; 1.0111x over previous
#include <cuda_runtime.h>

// max_general_2x2: reference relu chain collapses exactly to a
// 2x2 stride-2 fp32 max-pool: out = max(a,b,c,d).
//
// Input  x: (32, 64, 112, 112) fp32 (102.8 MB)
// Output  : (32, 64, 56, 56)   fp32 ( 25.7 MB)
//
// History: R4 (4xLDG.128/thread, contiguous) 19.58us, DRAM 71.7%, L1 41%.
//          R5 (8xLDG fragmented)  REGRESSED: L1 70%.
//          R6 (R4 + .CS hints)    neutral -> hints dropped.
// R7..R12: MLP=8 WITHOUT fragmentation — each thread does two R4-style
// chunks half the tensor apart. Warp footprint per region == R4.

#define NC_PLANES   (32 * 64)      // 2048 planes
#define IN_W        112
#define IN_PLANE    (112 * 112)    // 12544
#define OUT_W       56
#define V4_PER_ROW  (OUT_W / 4)    // 14 float4 per output row
#define TOTAL_V4    (NC_PLANES * OUT_W * V4_PER_ROW)  // 1,605,632
#define HALF_V4     (TOTAL_V4 / 2)                    //   802,816

__global__ __launch_bounds__(256) void maxpool2x2_kernel(
    const float* __restrict__ in, float4* __restrict__ out, int half)
{
    int idx = blockIdx.x * blockDim.x + threadIdx.x;
    if (idx >= half) return;

    // ---- chunk A: output float4 #idx ----
    int jA     = idx % V4_PER_ROW;
    int tA     = idx / V4_PER_ROW;
    int ohA    = tA % OUT_W;
    int planeA = tA / OUT_W;
    const float4* a0p = reinterpret_cast<const float4*>(
        in + (size_t)planeA * IN_PLANE + (2 * ohA) * IN_W + 8 * jA);
    const float4* a1p = reinterpret_cast<const float4*>(
        reinterpret_cast<const float*>(a0p) + IN_W);

    // ---- chunk B: output float4 #(idx + half) ----
    int idxB   = idx + half;
    int jB     = idxB % V4_PER_ROW;
    int tB     = idxB / V4_PER_ROW;
    int ohB    = tB % OUT_W;
    int planeB = tB / OUT_W;
    const float4* b0p = reinterpret_cast<const float4*>(
        in + (size_t)planeB * IN_PLANE + (2 * ohB) * IN_W + 8 * jB);
    const float4* b1p = reinterpret_cast<const float4*>(
        reinterpret_cast<const float*>(b0p) + IN_W);

    // 8 independent LDG.128, front-batched (MLP_p1 = 8); each group of 4
    // has the same contiguous warp footprint as R4.
    float4 a0 = a0p[0];
    float4 a1 = a0p[1];
    float4 a2 = a1p[0];
    float4 a3 = a1p[1];
    float4 b0 = b0p[0];
    float4 b1 = b0p[1];
    float4 b2 = b1p[0];
    float4 b3 = b1p[1];

    float4 oA, oB;
    oA.x = fmaxf(fmaxf(a0.x, a0.y), fmaxf(a2.x, a2.y));
    oA.y = fmaxf(fmaxf(a0.z, a0.w), fmaxf(a2.z, a2.w));
    oA.z = fmaxf(fmaxf(a1.x, a1.y), fmaxf(a3.x, a3.y));
    oA.w = fmaxf(fmaxf(a1.z, a1.w), fmaxf(a3.z, a3.w));
    oB.x = fmaxf(fmaxf(b0.x, b0.y), fmaxf(b2.x, b2.y));
    oB.y = fmaxf(fmaxf(b0.z, b0.w), fmaxf(b2.z, b2.w));
    oB.z = fmaxf(fmaxf(b1.x, b1.y), fmaxf(b3.x, b3.y));
    oB.w = fmaxf(fmaxf(b1.z, b1.w), fmaxf(b3.z, b3.w));

    out[idx]        = oA;
    out[idx + half] = oB;
}

extern "C" void kernel_launch(void* const* d_in, const int* in_sizes, int n_in,
                              void* d_out, int out_size)
{
    const float* x = (const float*)d_in[0];
    float4* out = (float4*)d_out;

    const int half = HALF_V4;               // 802,816 threads
    const int threads = 256;
    const int blocks = (half + threads - 1) / threads;  // 3136
    maxpool2x2_kernel<<<blocks, threads>>>(x, out, half);
}